// round 13
// baseline (speedup 1.0000x reference)
#include <cuda_runtime.h>
#include <cstdint>

#define B_   2
#define L_   2048
#define DIM_ 3072
#define H_   24
#define HD_  128
#define TOK  (B_ * L_)          // 4096
#define N_QKV (3 * DIM_)        // 9216

// ---------------- scratch (device globals — no allocation allowed) ----------
__device__ float g_q[(size_t)B_ * H_ * L_ * HD_];
__device__ float g_k[(size_t)B_ * H_ * L_ * HD_];
__device__ float g_v[(size_t)B_ * H_ * L_ * HD_];
__device__ float g_o[(size_t)TOK * DIM_];
// tf32-pre-rounded copies of inputs
__device__ float g_xr[(size_t)TOK * DIM_];
__device__ float g_wq[(size_t)N_QKV * DIM_];
__device__ float g_wp[(size_t)DIM_ * DIM_];

// ============================================================================
// helpers
// ============================================================================
__device__ __forceinline__ uint32_t f2tf(float f) {
    uint32_t r; asm("cvt.rna.tf32.f32 %0, %1;" : "=r"(r) : "f"(f)); return r;
}
__device__ __forceinline__ void mma_tf32(float* d, const uint32_t* a,
                                         uint32_t b0, uint32_t b1) {
    asm volatile(
        "mma.sync.aligned.m16n8k8.row.col.f32.tf32.tf32.f32 "
        "{%0,%1,%2,%3}, {%4,%5,%6,%7}, {%8,%9}, {%0,%1,%2,%3};"
        : "+f"(d[0]), "+f"(d[1]), "+f"(d[2]), "+f"(d[3])
        : "r"(a[0]), "r"(a[1]), "r"(a[2]), "r"(a[3]), "r"(b0), "r"(b1));
}
__device__ __forceinline__ uint32_t smem_u32(const void* p) {
    uint32_t a;
    asm("{ .reg .u64 t; cvta.to.shared.u64 t, %1; cvt.u32.u64 %0, t; }"
        : "=r"(a) : "l"(p));
    return a;
}
__device__ __forceinline__ void ldsm4(uint32_t* d, uint32_t saddr) {
    asm volatile("ldmatrix.sync.aligned.m8n8.x4.shared.b16 {%0,%1,%2,%3}, [%4];"
        : "=r"(d[0]), "=r"(d[1]), "=r"(d[2]), "=r"(d[3]) : "r"(saddr));
}
__device__ __forceinline__ void cpa16(uint32_t s, const float* g) {
    asm volatile("cp.async.cg.shared.global [%0], [%1], 16;"
                 :: "r"(s), "l"(g) : "memory");
}
#define CP_COMMIT() asm volatile("cp.async.commit_group;" ::: "memory")
#define CP_WAIT1()  asm volatile("cp.async.wait_group 1;" ::: "memory")

// ============================================================================
// pre-round inputs to tf32 (RNA)
// ============================================================================
__global__ __launch_bounds__(256) void round_tf32(
    const float4* __restrict__ in, float4* __restrict__ out, int n4)
{
    int i = blockIdx.x * 256 + threadIdx.x;
    if (i < n4) {
        float4 v = in[i];
        out[i] = make_float4(__uint_as_float(f2tf(v.x)), __uint_as_float(f2tf(v.y)),
                             __uint_as_float(f2tf(v.z)), __uint_as_float(f2tf(v.w)));
    }
}

// ============================================================================
// tf32 mma.sync GEMM, CUTLASS-shape: BM=128, BN=256, BK=32, 256 thr, 1 CTA/SM.
// 8 warps (2m x 4n), warp tile 64x64, acc[4][8][4]=128 regs.
// 3-stage cp.async ring (55296 B/stage), barrier once per 32-K.
// In-warp software pipeline: ldsm frags for sub-iter i+1 before MMAs of i.
// SMEM row stride 36 floats (144 B): 16B-aligned, ldmatrix conflict-free.
// MODE 0: C -> Cout row-major. MODE 1: scatter into g_q/g_k/g_v.
// ============================================================================
#define ASTRIDE  36
#define A_FL     (128 * ASTRIDE)            // 4608 floats
#define B_FL     (256 * ASTRIDE)            // 9216 floats
#define STG_FL   (A_FL + B_FL)              // 13824 floats
#define STG_B    (STG_FL * 4)               // 55296 bytes
#define GEMM_SMEM (3 * STG_B)               // 165888 bytes

template <int MODE>
__global__ __launch_bounds__(256, 1) void gemm_mma(
    const float* __restrict__ A, const float* __restrict__ W,
    const float* __restrict__ bias, float* __restrict__ Cout,
    int M, int N, int K)
{
    extern __shared__ float dsm[];

    const int tid = threadIdx.x;
    const int wid = tid >> 5, lane = tid & 31;
    const int wm = wid >> 2, wn = wid & 3;          // 2 x 4 warp grid
    const int qr = lane >> 2, c4 = lane & 3;
    const int row0 = blockIdx.y * 128;
    const int col0 = blockIdx.x * 256;
    const int NSTG = K / 32;

    // copy lane mapping: id -> row = id>>3, 16B chunk (id&7)
    const int crow = tid >> 3;          // 0..31
    const int cc4  = (tid & 7) * 4;     // 0,4,..,28

    const int lmr = (lane & 7) + (lane & 8);
    const int lmc = (lane >> 4) << 2;
    const uint32_t lmoff = (uint32_t)(lmr * ASTRIDE + lmc) * 4;
    const uint32_t sBase = smem_u32(dsm);

    const float* ga = A + (size_t)(row0 + crow) * K + cc4;
    const float* gb = W + (size_t)(col0 + crow) * K + cc4;
    const uint32_t dA = (uint32_t)(crow * ASTRIDE + cc4) * 4;
    const uint32_t dRow32 = (uint32_t)(32 * ASTRIDE) * 4;

    float acc[4][8][4];
#pragma unroll
    for (int mm = 0; mm < 4; mm++)
#pragma unroll
        for (int nn = 0; nn < 8; nn++)
#pragma unroll
            for (int q = 0; q < 4; q++) acc[mm][nn][q] = 0.f;

    // ---- issue one stage's copies ----
    auto issue_stage = [&](int st, int kt) {
        uint32_t s0 = sBase + st * STG_B + dA;
#pragma unroll
        for (int p = 0; p < 4; p++)                 // A: 128 rows
            cpa16(s0 + p * dRow32, ga + (size_t)(p * 32) * K + kt);
        uint32_t s1 = sBase + st * STG_B + A_FL * 4 + dA;
#pragma unroll
        for (int p = 0; p < 8; p++)                 // B: 256 rows
            cpa16(s1 + p * dRow32, gb + (size_t)(p * 32) * K + kt);
    };

    // ---- prologue: stages 0,1 ----
    issue_stage(0, 0);  CP_COMMIT();
    issue_stage(1, 32); CP_COMMIT();

    int stageIdx = 0;                    // s % 3
    for (int s = 0; s < NSTG; ++s) {
        CP_WAIT1();                      // stage s resident
        __syncthreads();                 // everyone done computing s-1

        // issue stage s+2 into buffer (s+2)%3 (freed by the sync above)
        if (s + 2 < NSTG) {
            int st = stageIdx + 2; if (st >= 3) st -= 3;
            issue_stage(st, (s + 2) * 32);
        }
        CP_COMMIT();                     // (possibly empty group — keeps count)

        const uint32_t sA = sBase + stageIdx * STG_B;
        const uint32_t sB = sA + A_FL * 4;

        // ---- software-pipelined compute: 4 sub-iters of 8-K ----
        uint32_t af[2][4][4], bf[2][4][4];
#pragma unroll
        for (int mm = 0; mm < 4; mm++)
            ldsm4(af[0][mm], sA + (uint32_t)((wm * 64 + mm * 16) * ASTRIDE * 4) + lmoff);
#pragma unroll
        for (int np = 0; np < 4; np++)
            ldsm4(bf[0][np], sB + (uint32_t)((wn * 64 + np * 16) * ASTRIDE * 4) + lmoff);

#pragma unroll
        for (int i = 0; i < 4; i++) {
            int cur = i & 1, nxt = cur ^ 1;
            if (i < 3) {
                uint32_t ko = (uint32_t)((i + 1) * 32);   // 8 K = 32 bytes
#pragma unroll
                for (int mm = 0; mm < 4; mm++)
                    ldsm4(af[nxt][mm], sA + (uint32_t)((wm * 64 + mm * 16) * ASTRIDE * 4)
                                       + ko + lmoff);
#pragma unroll
                for (int np = 0; np < 4; np++)
                    ldsm4(bf[nxt][np], sB + (uint32_t)((wn * 64 + np * 16) * ASTRIDE * 4)
                                       + ko + lmoff);
            }
#pragma unroll
            for (int np = 0; np < 4; np++)
#pragma unroll
                for (int mm = 0; mm < 4; mm++) {
                    mma_tf32(acc[mm][2 * np],     af[cur][mm], bf[cur][np][0], bf[cur][np][2]);
                    mma_tf32(acc[mm][2 * np + 1], af[cur][mm], bf[cur][np][1], bf[cur][np][3]);
                }
        }

        if (++stageIdx == 3) stageIdx = 0;
    }

    // ---- epilogue ----
#pragma unroll
    for (int nn = 0; nn < 8; nn++) {
        const int n = col0 + wn * 64 + nn * 8 + c4 * 2;
        const float b0 = bias[n], b1 = bias[n + 1];
#pragma unroll
        for (int mm = 0; mm < 4; mm++) {
            const int mrow = row0 + wm * 64 + mm * 16 + qr;
#pragma unroll
            for (int half = 0; half < 2; half++) {
                const int m = mrow + half * 8;
                float2 v = make_float2(acc[mm][nn][half * 2] + b0,
                                       acc[mm][nn][half * 2 + 1] + b1);
                if (MODE == 0) {
                    *reinterpret_cast<float2*>(&Cout[(size_t)m * N + n]) = v;
                } else {
                    int s   = n / DIM_;
                    int rem = n - s * DIM_;
                    int h   = rem >> 7;
                    int d   = rem & 127;
                    int b   = m >> 11;
                    int l   = m & 2047;
                    float* base = (s == 0) ? g_q : (s == 1) ? g_k : g_v;
                    *reinterpret_cast<float2*>(
                        &base[((size_t)(b * H_ + h) * L_ + l) * HD_ + d]) = v;
                }
            }
        }
    }
}

// ============================================================================
// RMSNorm + RoPE (unchanged)
// ============================================================================
__global__ __launch_bounds__(256) void rmsrope_kernel(
    const float* __restrict__ pe,
    const float* __restrict__ q_scale,
    const float* __restrict__ k_scale)
{
    int gw   = (blockIdx.x * blockDim.x + threadIdx.x) >> 5;
    int lane = threadIdx.x & 31;
    const int total = B_ * H_ * L_;
    bool is_k = gw >= total;
    int row = is_k ? gw - total : gw;
    float* ptr = (is_k ? g_k : g_q) + (size_t)row * HD_;
    const float* scale = is_k ? k_scale : q_scale;
    int l = row & (L_ - 1);

    float4 v = *reinterpret_cast<float4*>(&ptr[lane * 4]);
    float ss = v.x * v.x + v.y * v.y + v.z * v.z + v.w * v.w;
#pragma unroll
    for (int o = 16; o; o >>= 1) ss += __shfl_xor_sync(~0u, ss, o);
    float rrms = rsqrtf(ss * (1.0f / 128.0f) + 1e-6f);

    float4 sc = *reinterpret_cast<const float4*>(&scale[lane * 4]);
    v.x *= rrms * sc.x; v.y *= rrms * sc.y;
    v.z *= rrms * sc.z; v.w *= rrms * sc.w;

    const float* pe_l = pe + (size_t)l * 256;
    int i0 = lane * 2;
    float4 m0 = *reinterpret_cast<const float4*>(&pe_l[i0 * 4]);
    float o0 = m0.x * v.x + m0.y * v.y;
    float o1 = m0.z * v.x + m0.w * v.y;
    int i1 = i0 + 1;
    float4 m1 = *reinterpret_cast<const float4*>(&pe_l[i1 * 4]);
    float o2 = m1.x * v.z + m1.y * v.w;
    float o3 = m1.z * v.z + m1.w * v.w;

    *reinterpret_cast<float4*>(&ptr[lane * 4]) = make_float4(o0, o1, o2, o3);
}

// ============================================================================
// Flash attention, tf32 mma.sync (unchanged from round 12)
// ============================================================================
#define AQ_STR 132
#define AP_STR 68
#define ATTN_SMEM ((128 * AQ_STR + 2 * 64 * AQ_STR) * 4)

__global__ __launch_bounds__(256, 1) void attn_mma()
{
    extern __shared__ float sm[];
    float* Qs = sm;                        // 128 x 132 (later reused as Ps)
    float* Ks = sm + 128 * AQ_STR;         // 64 x 132
    float* Vs = Ks + 64 * AQ_STR;          // 64 x 132

    const int tid = threadIdx.x, w = tid >> 5, lane = tid & 31;
    const int qr = lane >> 2, c4 = lane & 3;
    const int q0 = blockIdx.x * 128;
    const int h = blockIdx.y, b = blockIdx.z;

    const size_t hoff = (size_t)(b * H_ + h) * L_ * HD_;
    const float* qg = g_q + hoff;
    const float* kg = g_k + hoff;
    const float* vg = g_v + hoff;

    const float scl = 0.08838834764831845f;   // 1/sqrt(128), folded into Q

    const int lmr = (lane & 7) + (lane & 8);
    const int lmc = (lane >> 4) << 2;
    const uint32_t lmQ = (uint32_t)(lmr * AQ_STR + lmc) * 4;
    const uint32_t lmP = (uint32_t)(lmr * AP_STR + lmc) * 4;
    const uint32_t sQ = smem_u32(sm);
    const uint32_t sK = smem_u32(Ks);

#pragma unroll
    for (int p = 0; p < 16; p++) {
        int fi = tid + 256 * p;
        int r = fi >> 5, d4 = (fi & 31) * 4;
        float4 v = *reinterpret_cast<const float4*>(&qg[(size_t)(q0 + r) * HD_ + d4]);
        *reinterpret_cast<float4*>(&Qs[r * AQ_STR + d4]) =
            make_float4(__uint_as_float(f2tf(v.x * scl)),
                        __uint_as_float(f2tf(v.y * scl)),
                        __uint_as_float(f2tf(v.z * scl)),
                        __uint_as_float(f2tf(v.w * scl)));
    }
    __syncthreads();

    uint32_t qf[16][4];
    {
        uint32_t qbase = sQ + (uint32_t)(w * 16 * AQ_STR) * 4;
#pragma unroll
        for (int ks = 0; ks < 16; ks++)
            ldsm4(qf[ks], qbase + ks * 32 + lmQ);
    }

    float of[16][4];
#pragma unroll
    for (int nt = 0; nt < 16; nt++)
#pragma unroll
        for (int q = 0; q < 4; q++) of[nt][q] = 0.f;
    float m0 = -1e30f, m1 = -1e30f, l0 = 0.f, l1 = 0.f;

    for (int kt = 0; kt < L_; kt += 64) {
#pragma unroll
        for (int p = 0; p < 8; p++) {
            int fi = tid + 256 * p;
            int r = fi >> 5, d4 = (fi & 31) * 4;
            float4 kv = *reinterpret_cast<const float4*>(&kg[(size_t)(kt + r) * HD_ + d4]);
            *reinterpret_cast<float4*>(&Ks[r * AQ_STR + d4]) =
                make_float4(__uint_as_float(f2tf(kv.x)), __uint_as_float(f2tf(kv.y)),
                            __uint_as_float(f2tf(kv.z)), __uint_as_float(f2tf(kv.w)));
            float4 vv = *reinterpret_cast<const float4*>(&vg[(size_t)(kt + r) * HD_ + d4]);
            *reinterpret_cast<float4*>(&Vs[r * AQ_STR + d4]) =
                make_float4(__uint_as_float(f2tf(vv.x)), __uint_as_float(f2tf(vv.y)),
                            __uint_as_float(f2tf(vv.z)), __uint_as_float(f2tf(vv.w)));
        }
        __syncthreads();

        float sacc[8][4];
#pragma unroll
        for (int nn = 0; nn < 8; nn++)
#pragma unroll
            for (int q = 0; q < 4; q++) sacc[nn][q] = 0.f;

#pragma unroll
        for (int ks = 0; ks < 16; ks++) {
            uint32_t kb[4][4];
#pragma unroll
            for (int np = 0; np < 4; np++)
                ldsm4(kb[np], sK + (uint32_t)(np * 16 * AQ_STR) * 4 + ks * 32 + lmQ);
#pragma unroll
            for (int np = 0; np < 4; np++) {
                mma_tf32(sacc[2 * np],     qf[ks], kb[np][0], kb[np][2]);
                mma_tf32(sacc[2 * np + 1], qf[ks], kb[np][1], kb[np][3]);
            }
        }

        float mx0 = -1e30f, mx1 = -1e30f;
#pragma unroll
        for (int nn = 0; nn < 8; nn++) {
            mx0 = fmaxf(mx0, fmaxf(sacc[nn][0], sacc[nn][1]));
            mx1 = fmaxf(mx1, fmaxf(sacc[nn][2], sacc[nn][3]));
        }
        mx0 = fmaxf(mx0, __shfl_xor_sync(~0u, mx0, 1));
        mx0 = fmaxf(mx0, __shfl_xor_sync(~0u, mx0, 2));
        mx1 = fmaxf(mx1, __shfl_xor_sync(~0u, mx1, 1));
        mx1 = fmaxf(mx1, __shfl_xor_sync(~0u, mx1, 2));

        float nm0 = fmaxf(m0, mx0), nm1 = fmaxf(m1, mx1);
        float a0 = __expf(m0 - nm0), a1 = __expf(m1 - nm1);
        m0 = nm0; m1 = nm1;

        float s0 = 0.f, s1 = 0.f;
#pragma unroll
        for (int nn = 0; nn < 8; nn++) {
            sacc[nn][0] = __expf(sacc[nn][0] - nm0); s0 += sacc[nn][0];
            sacc[nn][1] = __expf(sacc[nn][1] - nm0); s0 += sacc[nn][1];
            sacc[nn][2] = __expf(sacc[nn][2] - nm1); s1 += sacc[nn][2];
            sacc[nn][3] = __expf(sacc[nn][3] - nm1); s1 += sacc[nn][3];
        }
        s0 += __shfl_xor_sync(~0u, s0, 1); s0 += __shfl_xor_sync(~0u, s0, 2);
        s1 += __shfl_xor_sync(~0u, s1, 1); s1 += __shfl_xor_sync(~0u, s1, 2);
        l0 = l0 * a0 + s0; l1 = l1 * a1 + s1;

#pragma unroll
        for (int nt = 0; nt < 16; nt++) {
            of[nt][0] *= a0; of[nt][1] *= a0;
            of[nt][2] *= a1; of[nt][3] *= a1;
        }

        {
            float* Ps = sm;
            int r0 = w * 16 + qr;
#pragma unroll
            for (int nn = 0; nn < 8; nn++) {
                int col = nn * 8 + c4 * 2;
                uint32_t p0 = f2tf(sacc[nn][0]), p1 = f2tf(sacc[nn][1]);
                *reinterpret_cast<uint2*>(&Ps[r0 * AP_STR + col]) = make_uint2(p0, p1);
                uint32_t p2 = f2tf(sacc[nn][2]), p3 = f2tf(sacc[nn][3]);
                *reinterpret_cast<uint2*>(&Ps[(r0 + 8) * AP_STR + col]) = make_uint2(p2, p3);
            }
        }
        __syncthreads();

        {
            uint32_t pbase = sQ + (uint32_t)(w * 16 * AP_STR) * 4;
#pragma unroll
            for (int ks = 0; ks < 8; ks++) {
                uint32_t pf[4];
                ldsm4(pf, pbase + ks * 32 + lmP);
#pragma unroll
                for (int nt = 0; nt < 16; nt++) {
                    uint32_t b0 = __float_as_uint(Vs[(ks * 8 + c4) * AQ_STR + nt * 8 + qr]);
                    uint32_t b1 = __float_as_uint(Vs[(ks * 8 + 4 + c4) * AQ_STR + nt * 8 + qr]);
                    mma_tf32(of[nt], pf, b0, b1);
                }
            }
        }
        __syncthreads();
    }

    // epilogue: write g_o already tf32-rounded (proj GEMM copies it raw)
    {
        float inv0 = 1.0f / l0, inv1 = 1.0f / l1;
        int r0 = q0 + w * 16 + qr;
        float* og0 = g_o + ((size_t)(b * L_) + r0) * DIM_ + h * HD_;
        float* og1 = og0 + (size_t)8 * DIM_;
#pragma unroll
        for (int nt = 0; nt < 16; nt++) {
            int d = nt * 8 + c4 * 2;
            *reinterpret_cast<float2*>(&og0[d]) = make_float2(
                __uint_as_float(f2tf(of[nt][0] * inv0)),
                __uint_as_float(f2tf(of[nt][1] * inv0)));
            *reinterpret_cast<float2*>(&og1[d]) = make_float2(
                __uint_as_float(f2tf(of[nt][2] * inv1)),
                __uint_as_float(f2tf(of[nt][3] * inv1)));
        }
    }
}

// ============================================================================
extern "C" void kernel_launch(void* const* d_in, const int* in_sizes, int n_in,
                              void* d_out, int out_size)
{
    const float* x       = (const float*)d_in[0];
    const float* pe      = (const float*)d_in[1];
    const float* Wqkv    = (const float*)d_in[2];
    const float* bqkv    = (const float*)d_in[3];
    const float* q_scale = (const float*)d_in[4];
    const float* k_scale = (const float*)d_in[5];
    const float* Wproj   = (const float*)d_in[6];
    const float* bproj   = (const float*)d_in[7];
    float* out = (float*)d_out;

    cudaFuncSetAttribute(gemm_mma<1>, cudaFuncAttributeMaxDynamicSharedMemorySize, GEMM_SMEM);
    cudaFuncSetAttribute(gemm_mma<0>, cudaFuncAttributeMaxDynamicSharedMemorySize, GEMM_SMEM);
    cudaFuncSetAttribute(attn_mma, cudaFuncAttributeMaxDynamicSharedMemorySize, ATTN_SMEM);

    // 0) pre-round x, Wqkv, Wproj to tf32 (RNA) in scratch
    {
        float* xr = nullptr; float* wq = nullptr; float* wp = nullptr;
        cudaGetSymbolAddress((void**)&xr, g_xr);
        cudaGetSymbolAddress((void**)&wq, g_wq);
        cudaGetSymbolAddress((void**)&wp, g_wp);
        int n4x = TOK * DIM_ / 4, n4q = N_QKV * DIM_ / 4, n4p = DIM_ * DIM_ / 4;
        round_tf32<<<(n4x + 255) / 256, 256>>>((const float4*)x, (float4*)xr, n4x);
        round_tf32<<<(n4q + 255) / 256, 256>>>((const float4*)Wqkv, (float4*)wq, n4q);
        round_tf32<<<(n4p + 255) / 256, 256>>>((const float4*)Wproj, (float4*)wp, n4p);
    }

    float* xr = nullptr; float* wq = nullptr; float* wp = nullptr; float* go = nullptr;
    cudaGetSymbolAddress((void**)&xr, g_xr);
    cudaGetSymbolAddress((void**)&wq, g_wq);
    cudaGetSymbolAddress((void**)&wp, g_wp);
    cudaGetSymbolAddress((void**)&go, g_o);

    // 1) QKV GEMM (cp.async + tf32 mma.sync, BN=256) + scatter
    {
        dim3 grid(N_QKV / 256, TOK / 128);
        gemm_mma<1><<<grid, 256, GEMM_SMEM>>>(xr, wq, bqkv, nullptr, TOK, N_QKV, DIM_);
    }
    // 2) RMSNorm + RoPE
    {
        int rows = 2 * B_ * H_ * L_;
        rmsrope_kernel<<<rows / 8, 256>>>(pe, q_scale, k_scale);
    }
    // 3) flash attention (tf32 mma.sync)
    {
        dim3 grid(L_ / 128, H_, B_);
        attn_mma<<<grid, 256, ATTN_SMEM>>>();
    }
    // 4) output projection (cp.async + tf32 mma.sync, BN=256)
    {
        dim3 grid(DIM_ / 256, TOK / 128);
        gemm_mma<0><<<grid, 256, GEMM_SMEM>>>(go, wp, bproj, out, TOK, DIM_, DIM_);
    }
}

// round 14
// speedup vs baseline: 1.4587x; 1.4587x over previous
#include <cuda_runtime.h>
#include <cuda_fp16.h>
#include <cstdint>

#define B_   2
#define L_   2048
#define DIM_ 3072
#define H_   24
#define HD_  128
#define TOK  (B_ * L_)          // 4096
#define N_QKV (3 * DIM_)        // 9216

// ---------------- scratch (device globals — no allocation allowed) ----------
__device__ float g_q[(size_t)B_ * H_ * L_ * HD_];
__device__ float g_k[(size_t)B_ * H_ * L_ * HD_];
__device__ float g_v[(size_t)B_ * H_ * L_ * HD_];
// fp16 copies for GEMM operands
__device__ __half g_xh[(size_t)TOK * DIM_];
__device__ __half g_wqh[(size_t)N_QKV * DIM_];
__device__ __half g_wph[(size_t)DIM_ * DIM_];
__device__ __half g_oh[(size_t)TOK * DIM_];

// ============================================================================
// helpers
// ============================================================================
__device__ __forceinline__ uint32_t f2tf(float f) {
    uint32_t r; asm("cvt.rna.tf32.f32 %0, %1;" : "=r"(r) : "f"(f)); return r;
}
__device__ __forceinline__ void mma_tf32(float* d, const uint32_t* a,
                                         uint32_t b0, uint32_t b1) {
    asm volatile(
        "mma.sync.aligned.m16n8k8.row.col.f32.tf32.tf32.f32 "
        "{%0,%1,%2,%3}, {%4,%5,%6,%7}, {%8,%9}, {%0,%1,%2,%3};"
        : "+f"(d[0]), "+f"(d[1]), "+f"(d[2]), "+f"(d[3])
        : "r"(a[0]), "r"(a[1]), "r"(a[2]), "r"(a[3]), "r"(b0), "r"(b1));
}
__device__ __forceinline__ void mma_f16(float* d, const uint32_t* a,
                                        uint32_t b0, uint32_t b1) {
    asm volatile(
        "mma.sync.aligned.m16n8k16.row.col.f32.f16.f16.f32 "
        "{%0,%1,%2,%3}, {%4,%5,%6,%7}, {%8,%9}, {%0,%1,%2,%3};"
        : "+f"(d[0]), "+f"(d[1]), "+f"(d[2]), "+f"(d[3])
        : "r"(a[0]), "r"(a[1]), "r"(a[2]), "r"(a[3]), "r"(b0), "r"(b1));
}
__device__ __forceinline__ uint32_t smem_u32(const void* p) {
    uint32_t a;
    asm("{ .reg .u64 t; cvta.to.shared.u64 t, %1; cvt.u32.u64 %0, t; }"
        : "=r"(a) : "l"(p));
    return a;
}
__device__ __forceinline__ void ldsm4(uint32_t* d, uint32_t saddr) {
    asm volatile("ldmatrix.sync.aligned.m8n8.x4.shared.b16 {%0,%1,%2,%3}, [%4];"
        : "=r"(d[0]), "=r"(d[1]), "=r"(d[2]), "=r"(d[3]) : "r"(saddr));
}
__device__ __forceinline__ void cpa16(uint32_t s, const void* g) {
    asm volatile("cp.async.cg.shared.global [%0], [%1], 16;"
                 :: "r"(s), "l"(g) : "memory");
}
#define CP_COMMIT() asm volatile("cp.async.commit_group;" ::: "memory")
#define CP_WAIT2()  asm volatile("cp.async.wait_group 2;" ::: "memory")

// ============================================================================
// convert fp32 -> fp16 (RN)
// ============================================================================
__global__ __launch_bounds__(256) void to_fp16(
    const float4* __restrict__ in, __half* __restrict__ out, int n4)
{
    int i = blockIdx.x * 256 + threadIdx.x;
    if (i < n4) {
        float4 v = in[i];
        __half2* o = reinterpret_cast<__half2*>(out + (size_t)i * 4);
        o[0] = __floats2half2_rn(v.x, v.y);
        o[1] = __floats2half2_rn(v.z, v.w);
    }
}

// ============================================================================
// fp16 mma.sync GEMM, cp.async 4-stage, 2 CTAs/SM.
// C[M,N] = A[M,K] @ W[N,K]^T + bias[N]; A, W are fp16.
// BM=128, BN=128, BK=32. 256 threads = 8 warps (2m x 4n), warp tile 64x32.
// m16n8k16. SMEM rows: 32 halves + 8 pad = 40 halves (80 B) — 16B-aligned
// cp.async dsts, ldmatrix conflict-free. 20480 B/stage, 4 stages = 80 KB/CTA.
// MODE 0: C -> Cout row-major. MODE 1: scatter into g_q/g_k/g_v (fp32).
// ============================================================================
#define HSTR 40
#define AT_HALVES (128 * HSTR)              // 5120 halves = 10240 B
#define STG_B (2 * AT_HALVES * 2)           // 20480 B per stage (A+B)
#define GEMM_SMEM (4 * STG_B)               // 81920 B

template <int MODE>
__global__ __launch_bounds__(256, 2) void gemm_h(
    const __half* __restrict__ A, const __half* __restrict__ W,
    const float* __restrict__ bias, float* __restrict__ Cout,
    int M, int N, int K)
{
    extern __shared__ __half hsm[];

    const int tid = threadIdx.x;
    const int wid = tid >> 5, lane = tid & 31;
    const int wm = wid >> 2, wn = wid & 3;          // 2 x 4 warp grid
    const int qr = lane >> 2, c4 = lane & 3;
    const int row0 = blockIdx.y * 128;
    const int col0 = blockIdx.x * 128;
    const int NSTG = K / 32;

    // copy mapping: crow = tid>>2 (0..63), chunk (tid&3)*8 halves
    const int crow = tid >> 2;
    const int cc8  = (tid & 3) * 8;

    const int lmr = (lane & 7) + (lane & 8);
    const uint32_t lmoff = (uint32_t)(lmr * HSTR + ((lane >> 4) << 3)) * 2;
    const uint32_t sBase = smem_u32(hsm);

    const __half* ga = A + (size_t)(row0 + crow) * K + cc8;
    const __half* gb = W + (size_t)(col0 + crow) * K + cc8;
    const uint32_t dOff = (uint32_t)(crow * HSTR + cc8) * 2;
    const uint32_t dRow64 = (uint32_t)(64 * HSTR) * 2;

    float acc[4][4][4];
#pragma unroll
    for (int mm = 0; mm < 4; mm++)
#pragma unroll
        for (int nn = 0; nn < 4; nn++)
#pragma unroll
            for (int q = 0; q < 4; q++) acc[mm][nn][q] = 0.f;

    auto issue_stage = [&](int st, int kt) {
        uint32_t s0 = sBase + st * STG_B + dOff;
        cpa16(s0, ga + kt);
        cpa16(s0 + dRow64, ga + (size_t)64 * K + kt);
        uint32_t s1 = s0 + AT_HALVES * 2;
        cpa16(s1, gb + kt);
        cpa16(s1 + dRow64, gb + (size_t)64 * K + kt);
    };

    // ---- prologue: stages 0..2 ----
#pragma unroll
    for (int st = 0; st < 3; st++) { issue_stage(st, st * 32); CP_COMMIT(); }

    for (int s = 0; s < NSTG; ++s) {
        CP_WAIT2();
        __syncthreads();

        if (s + 3 < NSTG) issue_stage((s + 3) & 3, (s + 3) * 32);
        CP_COMMIT();

        const uint32_t sA = sBase + (uint32_t)((s & 3) * STG_B);
        const uint32_t sB = sA + AT_HALVES * 2;

#pragma unroll
        for (int ki = 0; ki < 2; ki++) {            // two k16 iters per BK=32
            const uint32_t ko = (uint32_t)(ki * 16) * 2;
            uint32_t a[4][4], bb[2][4];
#pragma unroll
            for (int mm = 0; mm < 4; mm++)
                ldsm4(a[mm], sA + (uint32_t)((wm * 64 + mm * 16) * HSTR * 2)
                               + ko + lmoff);
#pragma unroll
            for (int np = 0; np < 2; np++)
                ldsm4(bb[np], sB + (uint32_t)((wn * 32 + np * 16) * HSTR * 2)
                                + ko + lmoff);
#pragma unroll
            for (int np = 0; np < 2; np++)
#pragma unroll
                for (int mm = 0; mm < 4; mm++) {
                    mma_f16(acc[mm][2 * np],     a[mm], bb[np][0], bb[np][2]);
                    mma_f16(acc[mm][2 * np + 1], a[mm], bb[np][1], bb[np][3]);
                }
        }
    }

    // ---- epilogue ----
#pragma unroll
    for (int nn = 0; nn < 4; nn++) {
        const int n = col0 + wn * 32 + nn * 8 + c4 * 2;
        const float b0 = bias[n], b1 = bias[n + 1];
#pragma unroll
        for (int mm = 0; mm < 4; mm++) {
            const int mrow = row0 + wm * 64 + mm * 16 + qr;
#pragma unroll
            for (int half = 0; half < 2; half++) {
                const int m = mrow + half * 8;
                float2 v = make_float2(acc[mm][nn][half * 2] + b0,
                                       acc[mm][nn][half * 2 + 1] + b1);
                if (MODE == 0) {
                    *reinterpret_cast<float2*>(&Cout[(size_t)m * N + n]) = v;
                } else {
                    int s   = n / DIM_;
                    int rem = n - s * DIM_;
                    int h   = rem >> 7;
                    int d   = rem & 127;
                    int b   = m >> 11;
                    int l   = m & 2047;
                    float* base = (s == 0) ? g_q : (s == 1) ? g_k : g_v;
                    *reinterpret_cast<float2*>(
                        &base[((size_t)(b * H_ + h) * L_ + l) * HD_ + d]) = v;
                }
            }
        }
    }
}

// ============================================================================
// RMSNorm + RoPE (unchanged)
// ============================================================================
__global__ __launch_bounds__(256) void rmsrope_kernel(
    const float* __restrict__ pe,
    const float* __restrict__ q_scale,
    const float* __restrict__ k_scale)
{
    int gw   = (blockIdx.x * blockDim.x + threadIdx.x) >> 5;
    int lane = threadIdx.x & 31;
    const int total = B_ * H_ * L_;
    bool is_k = gw >= total;
    int row = is_k ? gw - total : gw;
    float* ptr = (is_k ? g_k : g_q) + (size_t)row * HD_;
    const float* scale = is_k ? k_scale : q_scale;
    int l = row & (L_ - 1);

    float4 v = *reinterpret_cast<float4*>(&ptr[lane * 4]);
    float ss = v.x * v.x + v.y * v.y + v.z * v.z + v.w * v.w;
#pragma unroll
    for (int o = 16; o; o >>= 1) ss += __shfl_xor_sync(~0u, ss, o);
    float rrms = rsqrtf(ss * (1.0f / 128.0f) + 1e-6f);

    float4 sc = *reinterpret_cast<const float4*>(&scale[lane * 4]);
    v.x *= rrms * sc.x; v.y *= rrms * sc.y;
    v.z *= rrms * sc.z; v.w *= rrms * sc.w;

    const float* pe_l = pe + (size_t)l * 256;
    int i0 = lane * 2;
    float4 m0 = *reinterpret_cast<const float4*>(&pe_l[i0 * 4]);
    float o0 = m0.x * v.x + m0.y * v.y;
    float o1 = m0.z * v.x + m0.w * v.y;
    int i1 = i0 + 1;
    float4 m1 = *reinterpret_cast<const float4*>(&pe_l[i1 * 4]);
    float o2 = m1.x * v.z + m1.y * v.w;
    float o3 = m1.z * v.z + m1.w * v.w;

    *reinterpret_cast<float4*>(&ptr[lane * 4]) = make_float4(o0, o1, o2, o3);
}

// ============================================================================
// Flash attention, tf32 mma.sync (round-12 design; epilogue writes g_oh fp16)
// ============================================================================
#define AQ_STR 132
#define AP_STR 68
#define ATTN_SMEM ((128 * AQ_STR + 2 * 64 * AQ_STR) * 4)

__global__ __launch_bounds__(256, 1) void attn_mma()
{
    extern __shared__ float sm[];
    float* Qs = sm;                        // 128 x 132 (later reused as Ps)
    float* Ks = sm + 128 * AQ_STR;         // 64 x 132
    float* Vs = Ks + 64 * AQ_STR;          // 64 x 132

    const int tid = threadIdx.x, w = tid >> 5, lane = tid & 31;
    const int qr = lane >> 2, c4 = lane & 3;
    const int q0 = blockIdx.x * 128;
    const int h = blockIdx.y, b = blockIdx.z;

    const size_t hoff = (size_t)(b * H_ + h) * L_ * HD_;
    const float* qg = g_q + hoff;
    const float* kg = g_k + hoff;
    const float* vg = g_v + hoff;

    const float scl = 0.08838834764831845f;   // 1/sqrt(128), folded into Q

    const int lmr = (lane & 7) + (lane & 8);
    const int lmc = (lane >> 4) << 2;
    const uint32_t lmQ = (uint32_t)(lmr * AQ_STR + lmc) * 4;
    const uint32_t lmP = (uint32_t)(lmr * AP_STR + lmc) * 4;
    const uint32_t sQ = smem_u32(sm);
    const uint32_t sK = smem_u32(Ks);

#pragma unroll
    for (int p = 0; p < 16; p++) {
        int fi = tid + 256 * p;
        int r = fi >> 5, d4 = (fi & 31) * 4;
        float4 v = *reinterpret_cast<const float4*>(&qg[(size_t)(q0 + r) * HD_ + d4]);
        *reinterpret_cast<float4*>(&Qs[r * AQ_STR + d4]) =
            make_float4(__uint_as_float(f2tf(v.x * scl)),
                        __uint_as_float(f2tf(v.y * scl)),
                        __uint_as_float(f2tf(v.z * scl)),
                        __uint_as_float(f2tf(v.w * scl)));
    }
    __syncthreads();

    uint32_t qf[16][4];
    {
        uint32_t qbase = sQ + (uint32_t)(w * 16 * AQ_STR) * 4;
#pragma unroll
        for (int ks = 0; ks < 16; ks++)
            ldsm4(qf[ks], qbase + ks * 32 + lmQ);
    }

    float of[16][4];
#pragma unroll
    for (int nt = 0; nt < 16; nt++)
#pragma unroll
        for (int q = 0; q < 4; q++) of[nt][q] = 0.f;
    float m0 = -1e30f, m1 = -1e30f, l0 = 0.f, l1 = 0.f;

    for (int kt = 0; kt < L_; kt += 64) {
#pragma unroll
        for (int p = 0; p < 8; p++) {
            int fi = tid + 256 * p;
            int r = fi >> 5, d4 = (fi & 31) * 4;
            float4 kv = *reinterpret_cast<const float4*>(&kg[(size_t)(kt + r) * HD_ + d4]);
            *reinterpret_cast<float4*>(&Ks[r * AQ_STR + d4]) =
                make_float4(__uint_as_float(f2tf(kv.x)), __uint_as_float(f2tf(kv.y)),
                            __uint_as_float(f2tf(kv.z)), __uint_as_float(f2tf(kv.w)));
            float4 vv = *reinterpret_cast<const float4*>(&vg[(size_t)(kt + r) * HD_ + d4]);
            *reinterpret_cast<float4*>(&Vs[r * AQ_STR + d4]) =
                make_float4(__uint_as_float(f2tf(vv.x)), __uint_as_float(f2tf(vv.y)),
                            __uint_as_float(f2tf(vv.z)), __uint_as_float(f2tf(vv.w)));
        }
        __syncthreads();

        float sacc[8][4];
#pragma unroll
        for (int nn = 0; nn < 8; nn++)
#pragma unroll
            for (int q = 0; q < 4; q++) sacc[nn][q] = 0.f;

#pragma unroll
        for (int ks = 0; ks < 16; ks++) {
            uint32_t kb[4][4];
#pragma unroll
            for (int np = 0; np < 4; np++)
                ldsm4(kb[np], sK + (uint32_t)(np * 16 * AQ_STR) * 4 + ks * 32 + lmQ);
#pragma unroll
            for (int np = 0; np < 4; np++) {
                mma_tf32(sacc[2 * np],     qf[ks], kb[np][0], kb[np][2]);
                mma_tf32(sacc[2 * np + 1], qf[ks], kb[np][1], kb[np][3]);
            }
        }

        float mx0 = -1e30f, mx1 = -1e30f;
#pragma unroll
        for (int nn = 0; nn < 8; nn++) {
            mx0 = fmaxf(mx0, fmaxf(sacc[nn][0], sacc[nn][1]));
            mx1 = fmaxf(mx1, fmaxf(sacc[nn][2], sacc[nn][3]));
        }
        mx0 = fmaxf(mx0, __shfl_xor_sync(~0u, mx0, 1));
        mx0 = fmaxf(mx0, __shfl_xor_sync(~0u, mx0, 2));
        mx1 = fmaxf(mx1, __shfl_xor_sync(~0u, mx1, 1));
        mx1 = fmaxf(mx1, __shfl_xor_sync(~0u, mx1, 2));

        float nm0 = fmaxf(m0, mx0), nm1 = fmaxf(m1, mx1);
        float a0 = __expf(m0 - nm0), a1 = __expf(m1 - nm1);
        m0 = nm0; m1 = nm1;

        float s0 = 0.f, s1 = 0.f;
#pragma unroll
        for (int nn = 0; nn < 8; nn++) {
            sacc[nn][0] = __expf(sacc[nn][0] - nm0); s0 += sacc[nn][0];
            sacc[nn][1] = __expf(sacc[nn][1] - nm0); s0 += sacc[nn][1];
            sacc[nn][2] = __expf(sacc[nn][2] - nm1); s1 += sacc[nn][2];
            sacc[nn][3] = __expf(sacc[nn][3] - nm1); s1 += sacc[nn][3];
        }
        s0 += __shfl_xor_sync(~0u, s0, 1); s0 += __shfl_xor_sync(~0u, s0, 2);
        s1 += __shfl_xor_sync(~0u, s1, 1); s1 += __shfl_xor_sync(~0u, s1, 2);
        l0 = l0 * a0 + s0; l1 = l1 * a1 + s1;

#pragma unroll
        for (int nt = 0; nt < 16; nt++) {
            of[nt][0] *= a0; of[nt][1] *= a0;
            of[nt][2] *= a1; of[nt][3] *= a1;
        }

        {
            float* Ps = sm;
            int r0 = w * 16 + qr;
#pragma unroll
            for (int nn = 0; nn < 8; nn++) {
                int col = nn * 8 + c4 * 2;
                uint32_t p0 = f2tf(sacc[nn][0]), p1 = f2tf(sacc[nn][1]);
                *reinterpret_cast<uint2*>(&Ps[r0 * AP_STR + col]) = make_uint2(p0, p1);
                uint32_t p2 = f2tf(sacc[nn][2]), p3 = f2tf(sacc[nn][3]);
                *reinterpret_cast<uint2*>(&Ps[(r0 + 8) * AP_STR + col]) = make_uint2(p2, p3);
            }
        }
        __syncthreads();

        {
            uint32_t pbase = sQ + (uint32_t)(w * 16 * AP_STR) * 4;
#pragma unroll
            for (int ks = 0; ks < 8; ks++) {
                uint32_t pf[4];
                ldsm4(pf, pbase + ks * 32 + lmP);
#pragma unroll
                for (int nt = 0; nt < 16; nt++) {
                    uint32_t b0 = __float_as_uint(Vs[(ks * 8 + c4) * AQ_STR + nt * 8 + qr]);
                    uint32_t b1 = __float_as_uint(Vs[(ks * 8 + 4 + c4) * AQ_STR + nt * 8 + qr]);
                    mma_tf32(of[nt], pf, b0, b1);
                }
            }
        }
        __syncthreads();
    }

    // epilogue: write g_oh (fp16) for the fp16 proj GEMM
    {
        float inv0 = 1.0f / l0, inv1 = 1.0f / l1;
        int r0 = q0 + w * 16 + qr;
        __half* og0 = g_oh + ((size_t)(b * L_) + r0) * DIM_ + h * HD_;
        __half* og1 = og0 + (size_t)8 * DIM_;
#pragma unroll
        for (int nt = 0; nt < 16; nt++) {
            int d = nt * 8 + c4 * 2;
            *reinterpret_cast<__half2*>(&og0[d]) =
                __floats2half2_rn(of[nt][0] * inv0, of[nt][1] * inv0);
            *reinterpret_cast<__half2*>(&og1[d]) =
                __floats2half2_rn(of[nt][2] * inv1, of[nt][3] * inv1);
        }
    }
}

// ============================================================================
extern "C" void kernel_launch(void* const* d_in, const int* in_sizes, int n_in,
                              void* d_out, int out_size)
{
    const float* x       = (const float*)d_in[0];
    const float* pe      = (const float*)d_in[1];
    const float* Wqkv    = (const float*)d_in[2];
    const float* bqkv    = (const float*)d_in[3];
    const float* q_scale = (const float*)d_in[4];
    const float* k_scale = (const float*)d_in[5];
    const float* Wproj   = (const float*)d_in[6];
    const float* bproj   = (const float*)d_in[7];
    float* out = (float*)d_out;

    cudaFuncSetAttribute(gemm_h<1>, cudaFuncAttributeMaxDynamicSharedMemorySize, GEMM_SMEM);
    cudaFuncSetAttribute(gemm_h<0>, cudaFuncAttributeMaxDynamicSharedMemorySize, GEMM_SMEM);
    cudaFuncSetAttribute(attn_mma, cudaFuncAttributeMaxDynamicSharedMemorySize, ATTN_SMEM);

    __half* xh = nullptr; __half* wqh = nullptr; __half* wph = nullptr; __half* oh = nullptr;
    cudaGetSymbolAddress((void**)&xh, g_xh);
    cudaGetSymbolAddress((void**)&wqh, g_wqh);
    cudaGetSymbolAddress((void**)&wph, g_wph);
    cudaGetSymbolAddress((void**)&oh, g_oh);

    // 0) convert x, Wqkv, Wproj to fp16 scratch
    {
        int n4x = TOK * DIM_ / 4, n4q = N_QKV * DIM_ / 4, n4p = DIM_ * DIM_ / 4;
        to_fp16<<<(n4x + 255) / 256, 256>>>((const float4*)x, xh, n4x);
        to_fp16<<<(n4q + 255) / 256, 256>>>((const float4*)Wqkv, wqh, n4q);
        to_fp16<<<(n4p + 255) / 256, 256>>>((const float4*)Wproj, wph, n4p);
    }

    // 1) QKV GEMM (fp16 m16n8k16) + scatter
    {
        dim3 grid(N_QKV / 128, TOK / 128);
        gemm_h<1><<<grid, 256, GEMM_SMEM>>>(xh, wqh, bqkv, nullptr, TOK, N_QKV, DIM_);
    }
    // 2) RMSNorm + RoPE
    {
        int rows = 2 * B_ * H_ * L_;
        rmsrope_kernel<<<rows / 8, 256>>>(pe, q_scale, k_scale);
    }
    // 3) flash attention (tf32 mma.sync) -> writes g_oh fp16
    {
        dim3 grid(L_ / 128, H_, B_);
        attn_mma<<<grid, 256, ATTN_SMEM>>>();
    }
    // 4) output projection (fp16 m16n8k16)
    {
        dim3 grid(DIM_ / 128, TOK / 128);
        gemm_h<0><<<grid, 256, GEMM_SMEM>>>(oh, wph, bproj, out, TOK, DIM_, DIM_);
    }
}

// round 15
// speedup vs baseline: 1.9765x; 1.3550x over previous
#include <cuda_runtime.h>
#include <cuda_fp16.h>
#include <cstdint>

#define B_   2
#define L_   2048
#define DIM_ 3072
#define H_   24
#define HD_  128
#define TOK  (B_ * L_)          // 4096
#define N_QKV (3 * DIM_)        // 9216

// ---------------- scratch (device globals — no allocation allowed) ----------
__device__ float  g_q[(size_t)B_ * H_ * L_ * HD_];   // fp32, pre-rmsrope
__device__ float  g_k[(size_t)B_ * H_ * L_ * HD_];
__device__ __half g_qh[(size_t)B_ * H_ * L_ * HD_];  // fp16, post-rmsrope (q pre-scaled)
__device__ __half g_kh[(size_t)B_ * H_ * L_ * HD_];
__device__ __half g_vh[(size_t)B_ * H_ * L_ * HD_];
__device__ __half g_xh[(size_t)TOK * DIM_];
__device__ __half g_wqh[(size_t)N_QKV * DIM_];
__device__ __half g_wph[(size_t)DIM_ * DIM_];
__device__ __half g_oh[(size_t)TOK * DIM_];

// ============================================================================
// helpers
// ============================================================================
__device__ __forceinline__ void mma_f16(float* d, const uint32_t* a,
                                        uint32_t b0, uint32_t b1) {
    asm volatile(
        "mma.sync.aligned.m16n8k16.row.col.f32.f16.f16.f32 "
        "{%0,%1,%2,%3}, {%4,%5,%6,%7}, {%8,%9}, {%0,%1,%2,%3};"
        : "+f"(d[0]), "+f"(d[1]), "+f"(d[2]), "+f"(d[3])
        : "r"(a[0]), "r"(a[1]), "r"(a[2]), "r"(a[3]), "r"(b0), "r"(b1));
}
__device__ __forceinline__ uint32_t smem_u32(const void* p) {
    uint32_t a;
    asm("{ .reg .u64 t; cvta.to.shared.u64 t, %1; cvt.u32.u64 %0, t; }"
        : "=r"(a) : "l"(p));
    return a;
}
__device__ __forceinline__ void ldsm4(uint32_t* d, uint32_t saddr) {
    asm volatile("ldmatrix.sync.aligned.m8n8.x4.shared.b16 {%0,%1,%2,%3}, [%4];"
        : "=r"(d[0]), "=r"(d[1]), "=r"(d[2]), "=r"(d[3]) : "r"(saddr));
}
__device__ __forceinline__ void ldsm4t(uint32_t* d, uint32_t saddr) {
    asm volatile("ldmatrix.sync.aligned.m8n8.x4.trans.shared.b16 {%0,%1,%2,%3}, [%4];"
        : "=r"(d[0]), "=r"(d[1]), "=r"(d[2]), "=r"(d[3]) : "r"(saddr));
}
__device__ __forceinline__ void cpa16(uint32_t s, const void* g) {
    asm volatile("cp.async.cg.shared.global [%0], [%1], 16;"
                 :: "r"(s), "l"(g) : "memory");
}
#define CP_COMMIT() asm volatile("cp.async.commit_group;" ::: "memory")
#define CP_WAIT0()  asm volatile("cp.async.wait_group 0;" ::: "memory")
#define CP_WAIT1()  asm volatile("cp.async.wait_group 1;" ::: "memory")
#define CP_WAIT2()  asm volatile("cp.async.wait_group 2;" ::: "memory")

// ============================================================================
// convert fp32 -> fp16 (RN)
// ============================================================================
__global__ __launch_bounds__(256) void to_fp16(
    const float4* __restrict__ in, __half* __restrict__ out, int n4)
{
    int i = blockIdx.x * 256 + threadIdx.x;
    if (i < n4) {
        float4 v = in[i];
        __half2* o = reinterpret_cast<__half2*>(out + (size_t)i * 4);
        o[0] = __floats2half2_rn(v.x, v.y);
        o[1] = __floats2half2_rn(v.z, v.w);
    }
}

// ============================================================================
// fp16 mma.sync GEMM (round-14 structure), 2 CTAs/SM.
// MODE 0: C -> Cout. MODE 1: scatter q,k fp32; v fp16 -> g_vh.
// ============================================================================
#define HSTR 40
#define AT_HALVES (128 * HSTR)
#define STG_B (2 * AT_HALVES * 2)
#define GEMM_SMEM (4 * STG_B)               // 81920 B

template <int MODE>
__global__ __launch_bounds__(256, 2) void gemm_h(
    const __half* __restrict__ A, const __half* __restrict__ W,
    const float* __restrict__ bias, float* __restrict__ Cout,
    int M, int N, int K)
{
    extern __shared__ __half hsm[];

    const int tid = threadIdx.x;
    const int wid = tid >> 5, lane = tid & 31;
    const int wm = wid >> 2, wn = wid & 3;
    const int qr = lane >> 2, c4 = lane & 3;
    const int row0 = blockIdx.y * 128;
    const int col0 = blockIdx.x * 128;
    const int NSTG = K / 32;

    const int crow = tid >> 2;
    const int cc8  = (tid & 3) * 8;

    const int lmr = (lane & 7) + (lane & 8);
    const uint32_t lmoff = (uint32_t)(lmr * HSTR + ((lane >> 4) << 3)) * 2;
    const uint32_t sBase = smem_u32(hsm);

    const __half* ga = A + (size_t)(row0 + crow) * K + cc8;
    const __half* gb = W + (size_t)(col0 + crow) * K + cc8;
    const uint32_t dOff = (uint32_t)(crow * HSTR + cc8) * 2;
    const uint32_t dRow64 = (uint32_t)(64 * HSTR) * 2;

    float acc[4][4][4];
#pragma unroll
    for (int mm = 0; mm < 4; mm++)
#pragma unroll
        for (int nn = 0; nn < 4; nn++)
#pragma unroll
            for (int q = 0; q < 4; q++) acc[mm][nn][q] = 0.f;

    auto issue_stage = [&](int st, int kt) {
        uint32_t s0 = sBase + st * STG_B + dOff;
        cpa16(s0, ga + kt);
        cpa16(s0 + dRow64, ga + (size_t)64 * K + kt);
        uint32_t s1 = s0 + AT_HALVES * 2;
        cpa16(s1, gb + kt);
        cpa16(s1 + dRow64, gb + (size_t)64 * K + kt);
    };

#pragma unroll
    for (int st = 0; st < 3; st++) { issue_stage(st, st * 32); CP_COMMIT(); }

    for (int s = 0; s < NSTG; ++s) {
        CP_WAIT2();
        __syncthreads();

        if (s + 3 < NSTG) issue_stage((s + 3) & 3, (s + 3) * 32);
        CP_COMMIT();

        const uint32_t sA = sBase + (uint32_t)((s & 3) * STG_B);
        const uint32_t sB = sA + AT_HALVES * 2;

#pragma unroll
        for (int ki = 0; ki < 2; ki++) {
            const uint32_t ko = (uint32_t)(ki * 16) * 2;
            uint32_t a[4][4], bb[2][4];
#pragma unroll
            for (int mm = 0; mm < 4; mm++)
                ldsm4(a[mm], sA + (uint32_t)((wm * 64 + mm * 16) * HSTR * 2)
                               + ko + lmoff);
#pragma unroll
            for (int np = 0; np < 2; np++)
                ldsm4(bb[np], sB + (uint32_t)((wn * 32 + np * 16) * HSTR * 2)
                                + ko + lmoff);
#pragma unroll
            for (int np = 0; np < 2; np++)
#pragma unroll
                for (int mm = 0; mm < 4; mm++) {
                    mma_f16(acc[mm][2 * np],     a[mm], bb[np][0], bb[np][2]);
                    mma_f16(acc[mm][2 * np + 1], a[mm], bb[np][1], bb[np][3]);
                }
        }
    }

    // ---- epilogue ----
#pragma unroll
    for (int nn = 0; nn < 4; nn++) {
        const int n = col0 + wn * 32 + nn * 8 + c4 * 2;
        const float b0 = bias[n], b1 = bias[n + 1];
#pragma unroll
        for (int mm = 0; mm < 4; mm++) {
            const int mrow = row0 + wm * 64 + mm * 16 + qr;
#pragma unroll
            for (int half = 0; half < 2; half++) {
                const int m = mrow + half * 8;
                float2 v = make_float2(acc[mm][nn][half * 2] + b0,
                                       acc[mm][nn][half * 2 + 1] + b1);
                if (MODE == 0) {
                    *reinterpret_cast<float2*>(&Cout[(size_t)m * N + n]) = v;
                } else {
                    int s   = n / DIM_;
                    int rem = n - s * DIM_;
                    int h   = rem >> 7;
                    int d   = rem & 127;
                    int b   = m >> 11;
                    int l   = m & 2047;
                    size_t idx = ((size_t)(b * H_ + h) * L_ + l) * HD_ + d;
                    if (s == 2) {
                        *reinterpret_cast<__half2*>(&g_vh[idx]) =
                            __floats2half2_rn(v.x, v.y);
                    } else {
                        float* base = (s == 0) ? g_q : g_k;
                        *reinterpret_cast<float2*>(&base[idx]) = v;
                    }
                }
            }
        }
    }
}

// ============================================================================
// RMSNorm + RoPE: read fp32 g_q/g_k, write fp16 g_qh/g_kh (q pre-scaled)
// ============================================================================
__global__ __launch_bounds__(256) void rmsrope_kernel(
    const float* __restrict__ pe,
    const float* __restrict__ q_scale,
    const float* __restrict__ k_scale)
{
    int gw   = (blockIdx.x * blockDim.x + threadIdx.x) >> 5;
    int lane = threadIdx.x & 31;
    const int total = B_ * H_ * L_;
    bool is_k = gw >= total;
    int row = is_k ? gw - total : gw;
    const float* ptr = (is_k ? g_k : g_q) + (size_t)row * HD_;
    __half* outp = (is_k ? g_kh : g_qh) + (size_t)row * HD_;
    const float* scale = is_k ? k_scale : q_scale;
    int l = row & (L_ - 1);
    const float post = is_k ? 1.0f : 0.08838834764831845f;  // q: 1/sqrt(128)

    float4 v = *reinterpret_cast<const float4*>(&ptr[lane * 4]);
    float ss = v.x * v.x + v.y * v.y + v.z * v.z + v.w * v.w;
#pragma unroll
    for (int o = 16; o; o >>= 1) ss += __shfl_xor_sync(~0u, ss, o);
    float rrms = rsqrtf(ss * (1.0f / 128.0f) + 1e-6f);

    float4 sc = *reinterpret_cast<const float4*>(&scale[lane * 4]);
    v.x *= rrms * sc.x; v.y *= rrms * sc.y;
    v.z *= rrms * sc.z; v.w *= rrms * sc.w;

    const float* pe_l = pe + (size_t)l * 256;
    int i0 = lane * 2;
    float4 m0 = *reinterpret_cast<const float4*>(&pe_l[i0 * 4]);
    float o0 = (m0.x * v.x + m0.y * v.y) * post;
    float o1 = (m0.z * v.x + m0.w * v.y) * post;
    int i1 = i0 + 1;
    float4 m1 = *reinterpret_cast<const float4*>(&pe_l[i1 * 4]);
    float o2 = (m1.x * v.z + m1.y * v.w) * post;
    float o3 = (m1.z * v.z + m1.w * v.w) * post;

    __half2* oh = reinterpret_cast<__half2*>(&outp[lane * 4]);
    oh[0] = __floats2half2_rn(o0, o1);
    oh[1] = __floats2half2_rn(o2, o3);
}

// ============================================================================
// Flash attention, fp16 m16n8k16, cp.async double-buffered K/V.
// q-tile 128, kv-tile 64, 256 threads = 8 warps, warp owns 16 q-rows.
// Q (pre-scaled fp16) frags in regs. K B-frags ldmatrix; V via ldmatrix.trans.
// P fp16 in smem (overlaps dead Q). O in fp32 C-frags.
// smem: Q 128x136h | 2 x (K 64x136h + V 64x136h) = 104448 B.
// ============================================================================
#define QH_STR 136
#define PH_STR 72
#define Q_BYTES   (128 * QH_STR * 2)         // 34816
#define KMAT_B    (64 * QH_STR * 2)          // 17408
#define KV_STG    (2 * KMAT_B)               // 34816
#define ATTN_SMEM (Q_BYTES + 2 * KV_STG)     // 104448

__global__ __launch_bounds__(256, 1) void attn_h()
{
    extern __shared__ __half hs[];
    const uint32_t sQ  = smem_u32(hs);
    const uint32_t sKV = sQ + Q_BYTES;

    const int tid = threadIdx.x, w = tid >> 5, lane = tid & 31;
    const int qr = lane >> 2, c4 = lane & 3;
    const int q0 = blockIdx.x * 128;
    const int h = blockIdx.y, b = blockIdx.z;

    const size_t hoff = (size_t)(b * H_ + h) * L_ * HD_;
    const __half* qg = g_qh + hoff + (size_t)q0 * HD_;
    const __half* kg = g_kh + hoff;
    const __half* vg = g_vh + hoff;

    const int lmr = (lane & 7) + (lane & 8);
    const int lc8 = (lane >> 4) << 3;            // 0 or 8 halves

    // ---- prologue: Q via cp.async ----
    {
        int qrow = tid >> 1, qc = (tid & 1) * 64;
#pragma unroll
        for (int j = 0; j < 8; j++)
            cpa16(sQ + (uint32_t)(qrow * QH_STR + qc + j * 8) * 2,
                  qg + (size_t)qrow * HD_ + qc + j * 8);
        CP_COMMIT();
    }
    // KV tile issue helper
    const int crow = tid >> 2;
    const int cb   = (tid & 3) * 32;
    auto issue_kv = [&](int st, int kt) {
        uint32_t kd = sKV + st * KV_STG + (uint32_t)(crow * QH_STR + cb) * 2;
        const __half* ks = kg + (size_t)(kt + crow) * HD_ + cb;
        const __half* vs = vg + (size_t)(kt + crow) * HD_ + cb;
#pragma unroll
        for (int j = 0; j < 4; j++) {
            cpa16(kd + j * 16, ks + j * 8);
            cpa16(kd + KMAT_B + j * 16, vs + j * 8);
        }
    };
    issue_kv(0, 0);
    CP_COMMIT();

    CP_WAIT1();                     // Q resident
    __syncthreads();

    // ---- Q A-frags (held in regs) ----
    uint32_t qf[8][4];
    {
        uint32_t qbase = sQ + (uint32_t)((w * 16 + lmr) * QH_STR + lc8) * 2;
#pragma unroll
        for (int ks = 0; ks < 8; ks++)
            ldsm4(qf[ks], qbase + ks * 32);     // 16 halves = 32 B per step
    }

    float of[16][4];
#pragma unroll
    for (int nt = 0; nt < 16; nt++)
#pragma unroll
        for (int q = 0; q < 4; q++) of[nt][q] = 0.f;
    float m0 = -1e30f, m1 = -1e30f, l0 = 0.f, l1 = 0.f;

    for (int t = 0; t < L_ / 64; t++) {
        CP_WAIT0();                  // tile t resident
        __syncthreads();             // all warps past tile t-1 compute
        if (t + 1 < L_ / 64) issue_kv((t + 1) & 1, (t + 1) * 64);
        CP_COMMIT();

        const uint32_t sK = sKV + (t & 1) * KV_STG;
        const uint32_t sV = sK + KMAT_B;

        // ---- S = Q K^T (8 k16 steps) ----
        float sacc[8][4];
#pragma unroll
        for (int nn = 0; nn < 8; nn++)
#pragma unroll
            for (int q = 0; q < 4; q++) sacc[nn][q] = 0.f;

#pragma unroll
        for (int ks = 0; ks < 8; ks++) {
            uint32_t kb[4][4];
#pragma unroll
            for (int np = 0; np < 4; np++)
                ldsm4(kb[np], sK + (uint32_t)((np * 16 + lmr) * QH_STR + lc8) * 2
                                + ks * 32);
#pragma unroll
            for (int np = 0; np < 4; np++) {
                mma_f16(sacc[2 * np],     qf[ks], kb[np][0], kb[np][2]);
                mma_f16(sacc[2 * np + 1], qf[ks], kb[np][1], kb[np][3]);
            }
        }

        // ---- online softmax (rows in lane quads) ----
        float mx0 = -1e30f, mx1 = -1e30f;
#pragma unroll
        for (int nn = 0; nn < 8; nn++) {
            mx0 = fmaxf(mx0, fmaxf(sacc[nn][0], sacc[nn][1]));
            mx1 = fmaxf(mx1, fmaxf(sacc[nn][2], sacc[nn][3]));
        }
        mx0 = fmaxf(mx0, __shfl_xor_sync(~0u, mx0, 1));
        mx0 = fmaxf(mx0, __shfl_xor_sync(~0u, mx0, 2));
        mx1 = fmaxf(mx1, __shfl_xor_sync(~0u, mx1, 1));
        mx1 = fmaxf(mx1, __shfl_xor_sync(~0u, mx1, 2));

        float nm0 = fmaxf(m0, mx0), nm1 = fmaxf(m1, mx1);
        float a0 = __expf(m0 - nm0), a1 = __expf(m1 - nm1);
        m0 = nm0; m1 = nm1;

        float s0 = 0.f, s1 = 0.f;
#pragma unroll
        for (int nn = 0; nn < 8; nn++) {
            sacc[nn][0] = __expf(sacc[nn][0] - nm0); s0 += sacc[nn][0];
            sacc[nn][1] = __expf(sacc[nn][1] - nm0); s0 += sacc[nn][1];
            sacc[nn][2] = __expf(sacc[nn][2] - nm1); s1 += sacc[nn][2];
            sacc[nn][3] = __expf(sacc[nn][3] - nm1); s1 += sacc[nn][3];
        }
        s0 += __shfl_xor_sync(~0u, s0, 1); s0 += __shfl_xor_sync(~0u, s0, 2);
        s1 += __shfl_xor_sync(~0u, s1, 1); s1 += __shfl_xor_sync(~0u, s1, 2);
        l0 = l0 * a0 + s0; l1 = l1 * a1 + s1;

#pragma unroll
        for (int nt = 0; nt < 16; nt++) {
            of[nt][0] *= a0; of[nt][1] *= a0;
            of[nt][2] *= a1; of[nt][3] *= a1;
        }

        // ---- P (fp16) into smem (overlaps dead Q region) ----
        {
            int r0 = w * 16 + qr;
#pragma unroll
            for (int nn = 0; nn < 8; nn++) {
                int col = nn * 8 + c4 * 2;
                *reinterpret_cast<__half2*>(hs + r0 * PH_STR + col) =
                    __floats2half2_rn(sacc[nn][0], sacc[nn][1]);
                *reinterpret_cast<__half2*>(hs + (r0 + 8) * PH_STR + col) =
                    __floats2half2_rn(sacc[nn][2], sacc[nn][3]);
            }
        }
        __syncwarp();                // P is warp-private: rows w*16..w*16+15

        // ---- O += P V (4 k16 steps) ----
#pragma unroll
        for (int kv = 0; kv < 4; kv++) {
            uint32_t pf[4];
            ldsm4(pf, sQ + (uint32_t)((w * 16 + lmr) * PH_STR + kv * 16 + lc8) * 2);
#pragma unroll
            for (int nt2 = 0; nt2 < 8; nt2++) {
                uint32_t vb[4];
                ldsm4t(vb, sV + (uint32_t)((kv * 16 + lmr) * QH_STR + nt2 * 16 + lc8) * 2);
                mma_f16(of[2 * nt2],     pf, vb[0], vb[1]);
                mma_f16(of[2 * nt2 + 1], pf, vb[2], vb[3]);
            }
        }
    }

    // ---- epilogue: O/l -> g_oh fp16 ----
    {
        float inv0 = 1.0f / l0, inv1 = 1.0f / l1;
        int r0 = q0 + w * 16 + qr;
        __half* og0 = g_oh + ((size_t)(b * L_) + r0) * DIM_ + h * HD_;
        __half* og1 = og0 + (size_t)8 * DIM_;
#pragma unroll
        for (int nt = 0; nt < 16; nt++) {
            int d = nt * 8 + c4 * 2;
            *reinterpret_cast<__half2*>(&og0[d]) =
                __floats2half2_rn(of[nt][0] * inv0, of[nt][1] * inv0);
            *reinterpret_cast<__half2*>(&og1[d]) =
                __floats2half2_rn(of[nt][2] * inv1, of[nt][3] * inv1);
        }
    }
}

// ============================================================================
extern "C" void kernel_launch(void* const* d_in, const int* in_sizes, int n_in,
                              void* d_out, int out_size)
{
    const float* x       = (const float*)d_in[0];
    const float* pe      = (const float*)d_in[1];
    const float* Wqkv    = (const float*)d_in[2];
    const float* bqkv    = (const float*)d_in[3];
    const float* q_scale = (const float*)d_in[4];
    const float* k_scale = (const float*)d_in[5];
    const float* Wproj   = (const float*)d_in[6];
    const float* bproj   = (const float*)d_in[7];
    float* out = (float*)d_out;

    cudaFuncSetAttribute(gemm_h<1>, cudaFuncAttributeMaxDynamicSharedMemorySize, GEMM_SMEM);
    cudaFuncSetAttribute(gemm_h<0>, cudaFuncAttributeMaxDynamicSharedMemorySize, GEMM_SMEM);
    cudaFuncSetAttribute(attn_h, cudaFuncAttributeMaxDynamicSharedMemorySize, ATTN_SMEM);

    __half* xh = nullptr; __half* wqh = nullptr; __half* wph = nullptr; __half* oh = nullptr;
    cudaGetSymbolAddress((void**)&xh, g_xh);
    cudaGetSymbolAddress((void**)&wqh, g_wqh);
    cudaGetSymbolAddress((void**)&wph, g_wph);
    cudaGetSymbolAddress((void**)&oh, g_oh);

    // 0) convert x, Wqkv, Wproj to fp16 scratch
    {
        int n4x = TOK * DIM_ / 4, n4q = N_QKV * DIM_ / 4, n4p = DIM_ * DIM_ / 4;
        to_fp16<<<(n4x + 255) / 256, 256>>>((const float4*)x, xh, n4x);
        to_fp16<<<(n4q + 255) / 256, 256>>>((const float4*)Wqkv, wqh, n4q);
        to_fp16<<<(n4p + 255) / 256, 256>>>((const float4*)Wproj, wph, n4p);
    }

    // 1) QKV GEMM (fp16) + scatter (q,k fp32; v fp16)
    {
        dim3 grid(N_QKV / 128, TOK / 128);
        gemm_h<1><<<grid, 256, GEMM_SMEM>>>(xh, wqh, bqkv, nullptr, TOK, N_QKV, DIM_);
    }
    // 2) RMSNorm + RoPE -> fp16 q (pre-scaled), k
    {
        int rows = 2 * B_ * H_ * L_;
        rmsrope_kernel<<<rows / 8, 256>>>(pe, q_scale, k_scale);
    }
    // 3) flash attention (fp16 m16n8k16, cp.async)
    {
        dim3 grid(L_ / 128, H_, B_);
        attn_h<<<grid, 256, ATTN_SMEM>>>();
    }
    // 4) output projection (fp16)
    {
        dim3 grid(DIM_ / 128, TOK / 128);
        gemm_h<0><<<grid, 256, GEMM_SMEM>>>(oh, wph, bproj, out, TOK, DIM_, DIM_);
    }
}